// round 5
// baseline (speedup 1.0000x reference)
#include <cuda_runtime.h>
#include <cstdint>
#include <cstddef>

#define B_   2048
#define E_   512
#define EMB_ 256
#define AR_  1024
#define H256_ 256
#define H32_  32
#define NT_   256

// Scratch (no cudaMalloc allowed)
__device__ float g_W12[AR_ * H32_];  // W_fc1 @ W_fc2
__device__ float g_bvec[H32_];       // b_fc1 @ W_fc2 + b_fc2
__device__ float g_w[B_ * EMB_];     // W_conv @ query[b]
__device__ float g_c0[B_];           // b_conv . query[b]

// ---------------------------------------------------------------------------
// Threefry2x32-20, JAX partitionable variant: counter (hi=0, lo=index),
// output = out0 ^ out1, key = (0, 42).
// ---------------------------------------------------------------------------
__device__ __forceinline__ uint32_t rotl32(uint32_t x, int r) {
    return (x << r) | (x >> (32 - r));
}

__device__ __forceinline__ uint32_t threefry_bits(uint32_t k0, uint32_t k1,
                                                  uint32_t c0, uint32_t c1) {
    uint32_t ks2 = k0 ^ k1 ^ 0x1BD11BDAu;
    uint32_t x0 = c0 + k0;
    uint32_t x1 = c1 + k1;
#define TF_RND(r) { x0 += x1; x1 = rotl32(x1, (r)); x1 ^= x0; }
    TF_RND(13) TF_RND(15) TF_RND(26) TF_RND(6)
    x0 += k1;  x1 += ks2 + 1u;
    TF_RND(17) TF_RND(29) TF_RND(16) TF_RND(24)
    x0 += ks2; x1 += k0 + 2u;
    TF_RND(13) TF_RND(15) TF_RND(26) TF_RND(6)
    x0 += k0;  x1 += k1 + 3u;
    TF_RND(17) TF_RND(29) TF_RND(16) TF_RND(24)
    x0 += k1;  x1 += ks2 + 4u;
    TF_RND(13) TF_RND(15) TF_RND(26) TF_RND(6)
    x0 += ks2; x1 += k0 + 5u;
#undef TF_RND
    return x0 ^ x1;
}

__device__ __forceinline__ float gumbel_from_index(uint32_t idx) {
    uint32_t bits = threefry_bits(0u, 42u, 0u, idx);
    float u = __uint_as_float((bits >> 9) | 0x3f800000u) - 1.0f;
    const float tiny = 1.17549435e-38f;
    u = fmaxf(tiny, u + tiny);
    return -logf(-logf(u));
}

// ---------------------------------------------------------------------------
// P0: g_W12 = W_fc1 @ W_fc2 (1024x32), g_bvec = b_fc1 @ W_fc2 + b_fc2.
// ---------------------------------------------------------------------------
__global__ __launch_bounds__(256)
void kernelP0(const float* __restrict__ W_fc1, const float* __restrict__ W_fc2,
              const float* __restrict__ b_fc1, const float* __restrict__ b_fc2) {
    __shared__ float s_w2[H256_ * H32_];   // 32KB
    const int tid = threadIdx.x;
    const int warp = tid >> 5, lane = tid & 31;
    for (int i = tid; i < H256_ * H32_; i += 256) s_w2[i] = W_fc2[i];
    __syncthreads();

    const int r = blockIdx.x * 8 + warp;
    const float* frow = W_fc1 + r * H256_;
    float a0 = 0.f, a1 = 0.f, a2 = 0.f, a3 = 0.f;
#pragma unroll 8
    for (int k0 = 0; k0 < H256_; k0 += 4) {
        float4 f = *(const float4*)(frow + k0);
        a0 += f.x * s_w2[(k0 + 0) * H32_ + lane];
        a1 += f.y * s_w2[(k0 + 1) * H32_ + lane];
        a2 += f.z * s_w2[(k0 + 2) * H32_ + lane];
        a3 += f.w * s_w2[(k0 + 3) * H32_ + lane];
    }
    g_W12[r * H32_ + lane] = (a0 + a1) + (a2 + a3);

    if (blockIdx.x == 0 && warp == 0) {
        float b0 = b_fc2[lane];
#pragma unroll 8
        for (int k = 0; k < H256_; k++) b0 += b_fc1[k] * s_w2[k * H32_ + lane];
        g_bvec[lane] = b0;
    }
}

// ---------------------------------------------------------------------------
// F: front-end for 4 b's per block (grid 512, 256 threads).
//   F1: t[q][j] = relu(b_func[j] + sum_k mask[q][k]*W_func[k][j])  (dense,
//       static unroll, weights read once per 4 b's)
//   F2: z2[q] = t[q]@W_fc2 + ar[q]@W12 + bvec  (2 warps per b, 640-k halves)
//   F3: LSTM (warp q) -> query; w = W_conv@query; c0 = b_conv.query
// Writes g_w[b], g_c0[b].
// ---------------------------------------------------------------------------
__global__ __launch_bounds__(256)
void kernelF(const float* __restrict__ ar, const int* __restrict__ utm,
             const float* __restrict__ W_func, const float* __restrict__ b_func,
             const float* __restrict__ W_conv, const float* __restrict__ b_conv,
             const float* __restrict__ W_fc2,
             const float* __restrict__ lk, const float* __restrict__ lb) {
    const int tid = threadIdx.x;
    const int warp = tid >> 5;
    const int lane = tid & 31;
    const int b0 = blockIdx.x * 4;

    __shared__ float s_m[4][NT_];      // masks as float
    __shared__ float s_t[4][H256_];    // relu outputs
    __shared__ float s_p[2][4][32];    // z2 partials (half, b, lane)
    __shared__ float s_q[4][32];       // queries
    __shared__ float s_c0[4];

    // load masks: 4*256 ints
#pragma unroll
    for (int q = 0; q < 4; q++)
        s_m[q][tid] = (float)utm[(b0 + q) * NT_ + tid];
    __syncthreads();

    // ---- F1: dense t, thread = column j, 4 b accumulators ----
    {
        float a0 = 0.f, a1 = 0.f, a2 = 0.f, a3 = 0.f;
#pragma unroll 8
        for (int k = 0; k < NT_; k++) {
            const float wv = W_func[k * H256_ + tid];
            a0 += wv * s_m[0][k];
            a1 += wv * s_m[1][k];
            a2 += wv * s_m[2][k];
            a3 += wv * s_m[3][k];
        }
        const float bf = b_func[tid];
        s_t[0][tid] = fmaxf(a0 + bf, 0.0f);
        s_t[1][tid] = fmaxf(a1 + bf, 0.0f);
        s_t[2][tid] = fmaxf(a2 + bf, 0.0f);
        s_t[3][tid] = fmaxf(a3 + bf, 0.0f);
    }
    __syncthreads();

    // ---- F2: z2 partials; warp w: b = w&3, half = w>>2 ----
    {
        const int q = warp & 3;
        const int half = warp >> 2;
        float acc0 = 0.f, acc1 = 0.f, acc2 = 0.f, acc3 = 0.f;
        if (half == 0) {
            // t part: k = 0..255
#pragma unroll 8
            for (int k = 0; k < H256_; k += 4) {
                acc0 += s_t[q][k + 0] * W_fc2[(k + 0) * H32_ + lane];
                acc1 += s_t[q][k + 1] * W_fc2[(k + 1) * H32_ + lane];
                acc2 += s_t[q][k + 2] * W_fc2[(k + 2) * H32_ + lane];
                acc3 += s_t[q][k + 3] * W_fc2[(k + 3) * H32_ + lane];
            }
            // ar part: r = 0..383
            const float* arow = ar + (size_t)(b0 + q) * AR_;
#pragma unroll 4
            for (int r = 0; r < 384; r += 4) {
                float4 a = *(const float4*)(arow + r);
                acc0 += a.x * g_W12[(r + 0) * H32_ + lane];
                acc1 += a.y * g_W12[(r + 1) * H32_ + lane];
                acc2 += a.z * g_W12[(r + 2) * H32_ + lane];
                acc3 += a.w * g_W12[(r + 3) * H32_ + lane];
            }
        } else {
            // ar part: r = 384..1023
            const float* arow = ar + (size_t)(b0 + q) * AR_;
#pragma unroll 4
            for (int r = 384; r < AR_; r += 4) {
                float4 a = *(const float4*)(arow + r);
                acc0 += a.x * g_W12[(r + 0) * H32_ + lane];
                acc1 += a.y * g_W12[(r + 1) * H32_ + lane];
                acc2 += a.z * g_W12[(r + 2) * H32_ + lane];
                acc3 += a.w * g_W12[(r + 3) * H32_ + lane];
            }
        }
        s_p[half][q][lane] = (acc0 + acc1) + (acc2 + acc3);
    }
    __syncthreads();

    // ---- F3a: warps 0..3: LSTM for b0+warp ----
    if (warp < 4) {
        float z = g_bvec[lane] + s_p[0][warp][lane] + s_p[1][warp][lane];
        float zi = lb[lane];
        float zg = lb[64 + lane];
        float zo = lb[96 + lane];
#pragma unroll
        for (int m = 0; m < 32; m++) {
            float v = __shfl_sync(0xffffffffu, z, m);
            zi += v * lk[m * 128 + lane];
            zg += v * lk[m * 128 + 64 + lane];
            zo += v * lk[m * 128 + 96 + lane];
        }
        float ig = 1.0f / (1.0f + expf(-zi));
        float gg = tanhf(zg);
        float og = 1.0f / (1.0f + expf(-zo));
        float c  = ig * gg;
        float h  = og * tanhf(c);
        s_q[warp][lane] = h;
        float part = b_conv[lane] * h;
#pragma unroll
        for (int s = 16; s > 0; s >>= 1) part += __shfl_xor_sync(0xffffffffu, part, s);
        if (lane == 0) s_c0[warp] = part;
    }
    __syncthreads();

    // ---- F3b: w[d] = W_conv[d,:].q, d = tid, reuse row across 4 b's ----
    {
        const float* wr = W_conv + tid * H32_;
        float4 wc[8];
#pragma unroll
        for (int m = 0; m < 8; m++) wc[m] = *(const float4*)(wr + m * 4);
#pragma unroll
        for (int q = 0; q < 4; q++) {
            float s0 = 0.f, s1 = 0.f;
#pragma unroll
            for (int m = 0; m < 8; m++) {
                s0 += wc[m].x * s_q[q][m * 4 + 0] + wc[m].y * s_q[q][m * 4 + 1];
                s1 += wc[m].z * s_q[q][m * 4 + 2] + wc[m].w * s_q[q][m * 4 + 3];
            }
            g_w[(b0 + q) * EMB_ + tid] = s0 + s1;
        }
    }
    if (tid < 4) g_c0[b0 + tid] = s_c0[tid];
}

// ---------------------------------------------------------------------------
// Kernel B: per-b block. y[e] = ee[b,e,:].w[b] + c0[b]; masked logit stores
// immediately; shuffle-based softmax + gumbel argmax (4 barriers total).
// ---------------------------------------------------------------------------
__global__ __launch_bounds__(256)
void kernelB(const float* __restrict__ ee, const int* __restrict__ tum,
             float* __restrict__ out, int mode) {
    const int b = blockIdx.x;
    const int tid = threadIdx.x;
    const int warp = tid >> 5;
    const int lane = tid & 31;

    __shared__ float ys[512];
    __shared__ float wred[8];
    __shared__ float wred2[8];
    __shared__ float wv[8];
    __shared__ int   wi[8];

    const float* wb = g_w + b * EMB_;
    const float4 w0 = *(const float4*)(wb + 4 * lane);
    const float4 w1 = *(const float4*)(wb + 128 + 4 * lane);
    const float cb = g_c0[b];
    const int tm = tum[b];
    const float4* eb = (const float4*)(ee + (size_t)b * E_ * EMB_);

#pragma unroll
    for (int it = 0; it < 16; it++) {
        const int e0 = it * 32 + warp * 4;
        float4 r0a = __ldcs(eb + (size_t)(e0 + 0) * 64 + lane);
        float4 r0b = __ldcs(eb + (size_t)(e0 + 0) * 64 + 32 + lane);
        float4 r1a = __ldcs(eb + (size_t)(e0 + 1) * 64 + lane);
        float4 r1b = __ldcs(eb + (size_t)(e0 + 1) * 64 + 32 + lane);
        float4 r2a = __ldcs(eb + (size_t)(e0 + 2) * 64 + lane);
        float4 r2b = __ldcs(eb + (size_t)(e0 + 2) * 64 + 32 + lane);
        float4 r3a = __ldcs(eb + (size_t)(e0 + 3) * 64 + lane);
        float4 r3b = __ldcs(eb + (size_t)(e0 + 3) * 64 + 32 + lane);

        float s0 = r0a.x * w0.x + r0a.y * w0.y + r0a.z * w0.z + r0a.w * w0.w
                 + r0b.x * w1.x + r0b.y * w1.y + r0b.z * w1.z + r0b.w * w1.w;
        float s1 = r1a.x * w0.x + r1a.y * w0.y + r1a.z * w0.z + r1a.w * w0.w
                 + r1b.x * w1.x + r1b.y * w1.y + r1b.z * w1.z + r1b.w * w1.w;
        float s2 = r2a.x * w0.x + r2a.y * w0.y + r2a.z * w0.z + r2a.w * w0.w
                 + r2b.x * w1.x + r2b.y * w1.y + r2b.z * w1.z + r2b.w * w1.w;
        float s3 = r3a.x * w0.x + r3a.y * w0.y + r3a.z * w0.z + r3a.w * w0.w
                 + r3b.x * w1.x + r3b.y * w1.y + r3b.z * w1.z + r3b.w * w1.w;
#pragma unroll
        for (int o = 16; o > 0; o >>= 1) {
            s0 += __shfl_xor_sync(0xffffffffu, s0, o);
            s1 += __shfl_xor_sync(0xffffffffu, s1, o);
            s2 += __shfl_xor_sync(0xffffffffu, s2, o);
            s3 += __shfl_xor_sync(0xffffffffu, s3, o);
        }
        if (lane == 0) {
            ys[e0 + 0] = s0 + cb;
            ys[e0 + 1] = s1 + cb;
            ys[e0 + 2] = s2 + cb;
            ys[e0 + 3] = s3 + cb;
        }
    }
    __syncthreads();

    const float y0 = ys[tid];
    const float y1 = ys[tid + 256];

    // masked logit stores: fire-and-forget, overlap with reductions
    const float mf = (float)tm;
    out[(size_t)b * 512 + tid]       = y0 * mf;
    out[(size_t)b * 512 + tid + 256] = y1 * mf;

    // gumbel noise (pure ALU, independent of reductions)
    const float gb0 = gumbel_from_index((uint32_t)(b * 512 + tid));
    const float gb1 = gumbel_from_index((uint32_t)(b * 512 + tid + 256));

    // ---- max ----
    float m = fmaxf(y0, y1);
#pragma unroll
    for (int o = 16; o > 0; o >>= 1) m = fmaxf(m, __shfl_xor_sync(0xffffffffu, m, o));
    if (lane == 0) wred[warp] = m;
    __syncthreads();
    float maxv = wred[0];
#pragma unroll
    for (int i2 = 1; i2 < 8; i2++) maxv = fmaxf(maxv, wred[i2]);

    // ---- exp + sum ----
    const float e0v = expf(y0 - maxv);
    const float e1v = expf(y1 - maxv);
    float s = e0v + e1v;
#pragma unroll
    for (int o = 16; o > 0; o >>= 1) s += __shfl_xor_sync(0xffffffffu, s, o);
    if (lane == 0) wred2[warp] = s;
    __syncthreads();
    float sumv = wred2[0];
#pragma unroll
    for (int i2 = 1; i2 < 8; i2++) sumv += wred2[i2];

    if (mode != 0) {
        // ---- probs + gumbel argmax (first-index tie-break) ----
        const float sc0 = e0v / sumv + gb0;
        const float sc1 = e1v / sumv + gb1;
        float bv; int bi;
        if (sc1 > sc0) { bv = sc1; bi = tid + 256; } else { bv = sc0; bi = tid; }
#pragma unroll
        for (int o = 16; o > 0; o >>= 1) {
            float ov = __shfl_xor_sync(0xffffffffu, bv, o);
            int   oi = __shfl_xor_sync(0xffffffffu, bi, o);
            if (ov > bv || (ov == bv && oi < bi)) { bv = ov; bi = oi; }
        }
        if (lane == 0) { wv[warp] = bv; wi[warp] = bi; }
        __syncthreads();
        if (tid == 0) {
            float fv = wv[0]; int fi = wi[0];
#pragma unroll
            for (int i2 = 1; i2 < 8; i2++) {
                if (wv[i2] > fv || (wv[i2] == fv && wi[i2] < fi)) { fv = wv[i2]; fi = wi[i2]; }
            }
            long long id = (long long)fi * (long long)tm;
            if (mode == 1) out[1048576 + b] = (float)id;
            else ((long long*)(out + 1048576))[b] = id;
        }
    }
}

// ---------------------------------------------------------------------------
extern "C" void kernel_launch(void* const* d_in, const int* in_sizes, int n_in,
                              void* d_out, int out_size) {
    const float* ar     = (const float*)d_in[0];
    const int*   utm    = (const int*)d_in[1];
    const int*   tum    = (const int*)d_in[2];
    const float* ee     = (const float*)d_in[3];
    const float* W_func = (const float*)d_in[4];
    const float* b_func = (const float*)d_in[5];
    const float* W_conv = (const float*)d_in[6];
    const float* b_conv = (const float*)d_in[7];
    const float* W_fc1  = (const float*)d_in[8];
    const float* b_fc1  = (const float*)d_in[9];
    const float* W_fc2  = (const float*)d_in[10];
    const float* b_fc2  = (const float*)d_in[11];
    const float* lk     = (const float*)d_in[12];
    // d_in[13] = lstm_recurrent: unused (h0 = 0)
    const float* lb     = (const float*)d_in[14];

    kernelP0<<<128, 256>>>(W_fc1, W_fc2, b_fc1, b_fc2);
    kernelF<<<512, 256>>>(ar, utm, W_func, b_func, W_conv, b_conv,
                          W_fc2, lk, lb);

    int mode = 0;
    if (out_size >= 1048576 + 4096)      mode = 2;
    else if (out_size >= 1048576 + 2048) mode = 1;
    kernelB<<<2048, 256>>>(ee, tum, (float*)d_out, mode);
}

// round 6
// speedup vs baseline: 1.1573x; 1.1573x over previous
#include <cuda_runtime.h>
#include <cstdint>
#include <cstddef>

#define B_   2048
#define E_   512
#define EMB_ 256
#define AR_  1024
#define H256_ 256
#define H32_  32
#define NT_   256

// Scratch (no cudaMalloc allowed)
__device__ float g_W12[AR_ * H32_];  // W_fc1 @ W_fc2
__device__ float g_bvec[H32_];       // b_fc1 @ W_fc2 + b_fc2
__device__ float g_u[B_ * H32_];     // ar[b] @ W12 + bvec

// ---------------------------------------------------------------------------
// Threefry2x32-20, JAX partitionable variant: counter (hi=0, lo=index),
// output = out0 ^ out1, key = (0, 42).
// ---------------------------------------------------------------------------
__device__ __forceinline__ uint32_t rotl32(uint32_t x, int r) {
    return (x << r) | (x >> (32 - r));
}

__device__ __forceinline__ uint32_t threefry_bits(uint32_t k0, uint32_t k1,
                                                  uint32_t c0, uint32_t c1) {
    uint32_t ks2 = k0 ^ k1 ^ 0x1BD11BDAu;
    uint32_t x0 = c0 + k0;
    uint32_t x1 = c1 + k1;
#define TF_RND(r) { x0 += x1; x1 = rotl32(x1, (r)); x1 ^= x0; }
    TF_RND(13) TF_RND(15) TF_RND(26) TF_RND(6)
    x0 += k1;  x1 += ks2 + 1u;
    TF_RND(17) TF_RND(29) TF_RND(16) TF_RND(24)
    x0 += ks2; x1 += k0 + 2u;
    TF_RND(13) TF_RND(15) TF_RND(26) TF_RND(6)
    x0 += k0;  x1 += k1 + 3u;
    TF_RND(17) TF_RND(29) TF_RND(16) TF_RND(24)
    x0 += k1;  x1 += ks2 + 4u;
    TF_RND(13) TF_RND(15) TF_RND(26) TF_RND(6)
    x0 += ks2; x1 += k0 + 5u;
#undef TF_RND
    return x0 ^ x1;
}

__device__ __forceinline__ float gumbel_from_index(uint32_t idx) {
    uint32_t bits = threefry_bits(0u, 42u, 0u, idx);
    float u = __uint_as_float((bits >> 9) | 0x3f800000u) - 1.0f;
    const float tiny = 1.17549435e-38f;
    u = fmaxf(tiny, u + tiny);
    return -logf(-logf(u));
}

// ---------------------------------------------------------------------------
// P0: g_W12 = W_fc1 @ W_fc2 (1024x32), g_bvec. Warp-per-row, no smem staging.
// grid 128 x 256 threads -> 1024 rows.
// ---------------------------------------------------------------------------
__global__ __launch_bounds__(256)
void kernelP0(const float* __restrict__ W_fc1, const float* __restrict__ W_fc2,
              const float* __restrict__ b_fc1, const float* __restrict__ b_fc2) {
    const int warp = threadIdx.x >> 5;
    const int lane = threadIdx.x & 31;
    const int r = blockIdx.x * 8 + warp;

    const float* frow = W_fc1 + r * H256_;
    float a0 = 0.f, a1 = 0.f, a2 = 0.f, a3 = 0.f;
#pragma unroll 8
    for (int k = 0; k < H256_; k += 4) {
        float4 f = *(const float4*)(frow + k);           // lane-uniform bcast
        a0 += f.x * W_fc2[(k + 0) * H32_ + lane];        // coalesced
        a1 += f.y * W_fc2[(k + 1) * H32_ + lane];
        a2 += f.z * W_fc2[(k + 2) * H32_ + lane];
        a3 += f.w * W_fc2[(k + 3) * H32_ + lane];
    }
    g_W12[r * H32_ + lane] = (a0 + a1) + (a2 + a3);

    if (blockIdx.x == 0 && warp == 0) {
        float b0 = b_fc2[lane];
#pragma unroll 8
        for (int k = 0; k < H256_; k++) b0 += b_fc1[k] * W_fc2[k * H32_ + lane];
        g_bvec[lane] = b0;
    }
}

// ---------------------------------------------------------------------------
// P1: g_u[b] = ar[b] @ W12 + bvec. 4 b's per block, 2 warps per b (512-k
// halves). grid 512 x 256 threads.
// ---------------------------------------------------------------------------
__global__ __launch_bounds__(256)
void kernelP1(const float* __restrict__ ar) {
    const int warp = threadIdx.x >> 5;
    const int lane = threadIdx.x & 31;
    const int q = warp & 3;
    const int half = warp >> 2;
    const int b0 = blockIdx.x * 4;

    __shared__ float s_p[2][4][32];

    const float* arow = ar + (size_t)(b0 + q) * AR_ + half * 512;
    const float* wp = g_W12 + (half * 512) * H32_;
    float a0 = 0.f, a1 = 0.f, a2 = 0.f, a3 = 0.f;
#pragma unroll 8
    for (int r = 0; r < 512; r += 4) {
        float4 a = *(const float4*)(arow + r);           // uniform bcast
        a0 += a.x * wp[(r + 0) * H32_ + lane];
        a1 += a.y * wp[(r + 1) * H32_ + lane];
        a2 += a.z * wp[(r + 2) * H32_ + lane];
        a3 += a.w * wp[(r + 3) * H32_ + lane];
    }
    s_p[half][q][lane] = (a0 + a1) + (a2 + a3);
    __syncthreads();

    if (warp < 4)
        g_u[(b0 + warp) * H32_ + lane] =
            s_p[0][warp][lane] + s_p[1][warp][lane] + g_bvec[lane];
}

// ---------------------------------------------------------------------------
// BF2: fused, 2 b's per block, grid 1024.
// Prologue (slim): dense 16-unrolled W_func pass for both masks -> t;
// z2 = t@W_fc2 (8-warp split) + g_u[b]; LSTM; w = W_conv@q; c0.
// Then per-b: stream ee, softmax, probs+gumbel argmax, masked writes.
// ---------------------------------------------------------------------------
__global__ __launch_bounds__(256)
void kernelBF2(const int* __restrict__ utm, const int* __restrict__ tum,
               const float* __restrict__ ee,
               const float* __restrict__ W_func, const float* __restrict__ b_func,
               const float* __restrict__ W_conv, const float* __restrict__ b_conv,
               const float* __restrict__ W_fc2,
               const float* __restrict__ lk, const float* __restrict__ lb,
               float* __restrict__ out, int mode) {
    const int b0 = blockIdx.x * 2;
    const int tid = threadIdx.x;
    const int warp = tid >> 5;
    const int lane = tid & 31;

    __shared__ float s_m[2][NT_];
    __shared__ float s_t[2][H256_];
    __shared__ float s_p[2][8][32];
    __shared__ float s_q[2][32];
    __shared__ float s_w[2][EMB_];
    __shared__ float s_c0[2];
    __shared__ float ys[512];
    __shared__ float wred[8];
    __shared__ float wred2[8];
    __shared__ float wv[8];
    __shared__ int   wi[8];

    // ---- masks ----
    s_m[0][tid] = (float)utm[(b0 + 0) * NT_ + tid];
    s_m[1][tid] = (float)utm[(b0 + 1) * NT_ + tid];
    __syncthreads();

    // ---- t (dense, 16 loads in flight, shared across both b's) ----
    {
        float ta0 = 0.f, ta1 = 0.f, ta2 = 0.f, ta3 = 0.f;
        float tb0 = 0.f, tb1 = 0.f, tb2 = 0.f, tb3 = 0.f;
#pragma unroll
        for (int kk = 0; kk < NT_; kk += 16) {
            float wv16[16];
#pragma unroll
            for (int i = 0; i < 16; i++)
                wv16[i] = W_func[(kk + i) * H256_ + tid];   // coalesced
#pragma unroll
            for (int i = 0; i < 16; i += 4) {
                ta0 += wv16[i + 0] * s_m[0][kk + i + 0];
                ta1 += wv16[i + 1] * s_m[0][kk + i + 1];
                ta2 += wv16[i + 2] * s_m[0][kk + i + 2];
                ta3 += wv16[i + 3] * s_m[0][kk + i + 3];
                tb0 += wv16[i + 0] * s_m[1][kk + i + 0];
                tb1 += wv16[i + 1] * s_m[1][kk + i + 1];
                tb2 += wv16[i + 2] * s_m[1][kk + i + 2];
                tb3 += wv16[i + 3] * s_m[1][kk + i + 3];
            }
        }
        const float bf = b_func[tid];
        s_t[0][tid] = fmaxf((ta0 + ta1) + (ta2 + ta3) + bf, 0.0f);
        s_t[1][tid] = fmaxf((tb0 + tb1) + (tb2 + tb3) + bf, 0.0f);
    }
    __syncthreads();

    // ---- z2 partials: warp w covers W_fc2 rows w*32..+31, both b's ----
    {
        float p0 = 0.f, p1 = 0.f;
#pragma unroll
        for (int jj = 0; jj < 32; jj++) {
            const int j = warp * 32 + jj;
            const float wf = W_fc2[j * H32_ + lane];
            p0 += s_t[0][j] * wf;
            p1 += s_t[1][j] * wf;
        }
        s_p[0][warp][lane] = p0;
        s_p[1][warp][lane] = p1;
    }
    __syncthreads();

    // ---- LSTM: warp q in {0,1} ----
    if (warp < 2) {
        float z = g_u[(b0 + warp) * H32_ + lane];   // includes bvec
#pragma unroll
        for (int w2 = 0; w2 < 8; w2++) z += s_p[warp][w2][lane];
        float zi = lb[lane];
        float zg = lb[64 + lane];
        float zo = lb[96 + lane];
#pragma unroll
        for (int m = 0; m < 32; m++) {
            float v = __shfl_sync(0xffffffffu, z, m);
            zi += v * lk[m * 128 + lane];
            zg += v * lk[m * 128 + 64 + lane];
            zo += v * lk[m * 128 + 96 + lane];
        }
        float ig = 1.0f / (1.0f + expf(-zi));
        float gg = tanhf(zg);
        float og = 1.0f / (1.0f + expf(-zo));
        float c  = ig * gg;
        float h  = og * tanhf(c);
        s_q[warp][lane] = h;
        float part = b_conv[lane] * h;
#pragma unroll
        for (int s = 16; s > 0; s >>= 1) part += __shfl_xor_sync(0xffffffffu, part, s);
        if (lane == 0) s_c0[warp] = part;
    }
    __syncthreads();

    // ---- w = W_conv @ q, row per thread, shared across both b's ----
    {
        const float* wr = W_conv + tid * H32_;
        float4 wc[8];
#pragma unroll
        for (int m = 0; m < 8; m++) wc[m] = *(const float4*)(wr + m * 4);
#pragma unroll
        for (int q = 0; q < 2; q++) {
            float s0 = 0.f, s1 = 0.f;
#pragma unroll
            for (int m = 0; m < 8; m++) {
                s0 += wc[m].x * s_q[q][m * 4 + 0] + wc[m].y * s_q[q][m * 4 + 1];
                s1 += wc[m].z * s_q[q][m * 4 + 2] + wc[m].w * s_q[q][m * 4 + 3];
            }
            s_w[q][tid] = s0 + s1;
        }
    }
    __syncthreads();

    // =========================== Stream both b's ===========================
    for (int q = 0; q < 2; q++) {
        const int b = b0 + q;
        const float4 w0 = *(const float4*)(&s_w[q][4 * lane]);
        const float4 w1 = *(const float4*)(&s_w[q][128 + 4 * lane]);
        const float cb = s_c0[q];
        const int tm = tum[b];
        const float4* eb = (const float4*)(ee + (size_t)b * E_ * EMB_);

#pragma unroll
        for (int it = 0; it < 16; it++) {
            const int e0 = it * 32 + warp * 4;
            float4 r0a = __ldcs(eb + (size_t)(e0 + 0) * 64 + lane);
            float4 r0b = __ldcs(eb + (size_t)(e0 + 0) * 64 + 32 + lane);
            float4 r1a = __ldcs(eb + (size_t)(e0 + 1) * 64 + lane);
            float4 r1b = __ldcs(eb + (size_t)(e0 + 1) * 64 + 32 + lane);
            float4 r2a = __ldcs(eb + (size_t)(e0 + 2) * 64 + lane);
            float4 r2b = __ldcs(eb + (size_t)(e0 + 2) * 64 + 32 + lane);
            float4 r3a = __ldcs(eb + (size_t)(e0 + 3) * 64 + lane);
            float4 r3b = __ldcs(eb + (size_t)(e0 + 3) * 64 + 32 + lane);

            float s0 = r0a.x * w0.x + r0a.y * w0.y + r0a.z * w0.z + r0a.w * w0.w
                     + r0b.x * w1.x + r0b.y * w1.y + r0b.z * w1.z + r0b.w * w1.w;
            float s1 = r1a.x * w0.x + r1a.y * w0.y + r1a.z * w0.z + r1a.w * w0.w
                     + r1b.x * w1.x + r1b.y * w1.y + r1b.z * w1.z + r1b.w * w1.w;
            float s2 = r2a.x * w0.x + r2a.y * w0.y + r2a.z * w0.z + r2a.w * w0.w
                     + r2b.x * w1.x + r2b.y * w1.y + r2b.z * w1.z + r2b.w * w1.w;
            float s3 = r3a.x * w0.x + r3a.y * w0.y + r3a.z * w0.z + r3a.w * w0.w
                     + r3b.x * w1.x + r3b.y * w1.y + r3b.z * w1.z + r3b.w * w1.w;
#pragma unroll
            for (int o = 16; o > 0; o >>= 1) {
                s0 += __shfl_xor_sync(0xffffffffu, s0, o);
                s1 += __shfl_xor_sync(0xffffffffu, s1, o);
                s2 += __shfl_xor_sync(0xffffffffu, s2, o);
                s3 += __shfl_xor_sync(0xffffffffu, s3, o);
            }
            if (lane == 0) {
                ys[e0 + 0] = s0 + cb;
                ys[e0 + 1] = s1 + cb;
                ys[e0 + 2] = s2 + cb;
                ys[e0 + 3] = s3 + cb;
            }
        }
        __syncthreads();

        const float y0 = ys[tid];
        const float y1 = ys[tid + 256];

        // masked logit stores: fire-and-forget
        const float mf = (float)tm;
        out[(size_t)b * 512 + tid]       = y0 * mf;
        out[(size_t)b * 512 + tid + 256] = y1 * mf;

        // gumbel noise (pure ALU)
        const float gb0 = gumbel_from_index((uint32_t)(b * 512 + tid));
        const float gb1 = gumbel_from_index((uint32_t)(b * 512 + tid + 256));

        // ---- max ----
        float m = fmaxf(y0, y1);
#pragma unroll
        for (int o = 16; o > 0; o >>= 1) m = fmaxf(m, __shfl_xor_sync(0xffffffffu, m, o));
        if (lane == 0) wred[warp] = m;
        __syncthreads();
        float maxv = wred[0];
#pragma unroll
        for (int i2 = 1; i2 < 8; i2++) maxv = fmaxf(maxv, wred[i2]);

        // ---- exp + sum ----
        const float e0v = expf(y0 - maxv);
        const float e1v = expf(y1 - maxv);
        float s = e0v + e1v;
#pragma unroll
        for (int o = 16; o > 0; o >>= 1) s += __shfl_xor_sync(0xffffffffu, s, o);
        if (lane == 0) wred2[warp] = s;
        __syncthreads();
        float sumv = wred2[0];
#pragma unroll
        for (int i2 = 1; i2 < 8; i2++) sumv += wred2[i2];

        if (mode != 0) {
            const float sc0 = e0v / sumv + gb0;
            const float sc1 = e1v / sumv + gb1;
            float bv; int bi;
            if (sc1 > sc0) { bv = sc1; bi = tid + 256; } else { bv = sc0; bi = tid; }
#pragma unroll
            for (int o = 16; o > 0; o >>= 1) {
                float ov = __shfl_xor_sync(0xffffffffu, bv, o);
                int   oi = __shfl_xor_sync(0xffffffffu, bi, o);
                if (ov > bv || (ov == bv && oi < bi)) { bv = ov; bi = oi; }
            }
            if (lane == 0) { wv[warp] = bv; wi[warp] = bi; }
            __syncthreads();
            if (tid == 0) {
                float fv = wv[0]; int fi = wi[0];
#pragma unroll
                for (int i2 = 1; i2 < 8; i2++) {
                    if (wv[i2] > fv || (wv[i2] == fv && wi[i2] < fi)) { fv = wv[i2]; fi = wi[i2]; }
                }
                long long id = (long long)fi * (long long)tm;
                if (mode == 1) out[1048576 + b] = (float)id;
                else ((long long*)(out + 1048576))[b] = id;
            }
        }
        __syncthreads();   // protect ys / wred reuse for next q
    }
}

// ---------------------------------------------------------------------------
extern "C" void kernel_launch(void* const* d_in, const int* in_sizes, int n_in,
                              void* d_out, int out_size) {
    const float* ar     = (const float*)d_in[0];
    const int*   utm    = (const int*)d_in[1];
    const int*   tum    = (const int*)d_in[2];
    const float* ee     = (const float*)d_in[3];
    const float* W_func = (const float*)d_in[4];
    const float* b_func = (const float*)d_in[5];
    const float* W_conv = (const float*)d_in[6];
    const float* b_conv = (const float*)d_in[7];
    const float* W_fc1  = (const float*)d_in[8];
    const float* b_fc1  = (const float*)d_in[9];
    const float* W_fc2  = (const float*)d_in[10];
    const float* b_fc2  = (const float*)d_in[11];
    const float* lk     = (const float*)d_in[12];
    // d_in[13] = lstm_recurrent: unused (h0 = 0)
    const float* lb     = (const float*)d_in[14];

    kernelP0<<<128, 256>>>(W_fc1, W_fc2, b_fc1, b_fc2);
    kernelP1<<<512, 256>>>(ar);

    int mode = 0;
    if (out_size >= 1048576 + 4096)      mode = 2;
    else if (out_size >= 1048576 + 2048) mode = 1;
    kernelBF2<<<1024, 256>>>(utm, tum, ee, W_func, b_func, W_conv, b_conv,
                             W_fc2, lk, lb, (float*)d_out, mode);
}